// round 11
// baseline (speedup 1.0000x reference)
#include <cuda_runtime.h>

#define MAX_N 262144
#define MAX_BLK (MAX_N / 256)
__device__ float g_cat[(size_t)MAX_N * 256];
__device__ float g_accum[(size_t)MAX_N * 32];
__device__ int   g_ent[(size_t)MAX_BLK * 26 * 256];
__device__ int   g_cnt[(size_t)MAX_BLK * 26];

typedef unsigned long long u64;

__device__ __forceinline__ u64 pk2(float a, float b) {
    u64 r;
    asm("mov.b64 %0, {%1, %2};" : "=l"(r)
        : "r"(__float_as_uint(a)), "r"(__float_as_uint(b)));
    return r;
}
__device__ __forceinline__ u64 dup2(float a) {
    u64 r; unsigned ai = __float_as_uint(a);
    asm("mov.b64 %0, {%1, %1};" : "=l"(r) : "r"(ai));
    return r;
}
__device__ __forceinline__ float2 up2(u64 v) {
    unsigned a, b;
    asm("mov.b64 {%0, %1}, %2;" : "=r"(a), "=r"(b) : "l"(v));
    return make_float2(__uint_as_float(a), __uint_as_float(b));
}
__device__ __forceinline__ void fma2(u64& d, u64 a, u64 b) {
    asm("fma.rn.f32x2 %0, %1, %2, %0;" : "+l"(d) : "l"(a), "l"(b));
}
__device__ __forceinline__ u64 addp(u64 a, u64 b) {
    u64 r;
    asm("add.rn.f32x2 %0, %1, %2;" : "=l"(r) : "l"(a), "l"(b));
    return r;
}
__device__ __forceinline__ u64 d2u(double d) { return __double_as_longlong(d); }

// ---------------------------------------------------------------------------
// build_list: one pass over nbr, compact valid non-self taps into per-(block,k)
// segments. Reused by all 4 conv layers. Entry = (ni << 8) | local_row.
// ---------------------------------------------------------------------------
__global__ __launch_bounds__(256)
void build_list_kernel(const int* __restrict__ nbr, int N)
{
    __shared__ int snb[256 * 27];
    __shared__ int cnt[26];

    const int t    = threadIdx.x;
    const int lane = t & 31;
    const int base = blockIdx.x * 256;

    if (t < 26) cnt[t] = 0;
    for (int i = t; i < 256 * 27; i += 256) {
        long long g = (long long)base * 27 + i;
        int v = -1;
        if (g < (long long)N * 27) v = __ldg(&nbr[g]);
        snb[i] = v;
    }
    __syncthreads();

#pragma unroll
    for (int k = 0; k < 27; k++) {
        if (k == 13) continue;
        const int s  = k - (k > 13);
        const int nb = snb[t * 27 + k];
        const bool valid = nb >= 0;
        unsigned m = __ballot_sync(0xffffffffu, valid);
        if (m) {
            int leader = __ffs(m) - 1;
            int wb = 0;
            if (lane == leader) wb = atomicAdd(&cnt[s], __popc(m));
            wb = __shfl_sync(0xffffffffu, wb, leader);
            if (valid) {
                int pos = wb + __popc(m & ((1u << lane) - 1));
                g_ent[((size_t)blockIdx.x * 26 + s) * 256 + pos] = (nb << 8) | t;
            }
        }
    }
    __syncthreads();
    if (t < 26) g_cnt[blockIdx.x * 26 + t] = cnt[t];
}

// ---------------------------------------------------------------------------
// blk1_dual: f1 = relu(LN(x@W1+b1)), f2 = relu(LN(x@W2+b2)) in one pass.
// ---------------------------------------------------------------------------
__global__ __launch_bounds__(256)
void blk1_dual_kernel(const float* __restrict__ x,
                      const float* __restrict__ W1, const float* __restrict__ b1,
                      const float* __restrict__ g1, const float* __restrict__ be1,
                      const float* __restrict__ W2, const float* __restrict__ b2,
                      const float* __restrict__ g2, const float* __restrict__ be2,
                      float* __restrict__ out, int N)
{
    constexpr int ROWS = 64, PX = 68, PW = 68;
    extern __shared__ float sm[];
    float* Xs = sm;
    float* Ws = sm + ROWS * PX;

    const int t    = threadIdx.x;
    const int cg   = t & 15;
    const int rg   = t >> 4;
    const int r0   = rg * 4;
    const int half = cg >> 3;
    const int c0   = (cg & 7) * 8;
    const int key  = rg & 7;
    const int base = blockIdx.x * ROWS;

    for (int idx = t; idx < 64 * 16; idx += 256) {
        int j = idx >> 4, q = idx & 15;
        int pq = (q >> 1) + ((q & 1) << 3);
        *(float4*)&Ws[j * PW + pq * 4]            = *(const float4*)&W1[j * 64 + q * 4];
        *(float4*)&Ws[64 * PW + j * PW + pq * 4]  = *(const float4*)&W2[j * 64 + q * 4];
    }
    for (int idx = t; idx < ROWS * 16; idx += 256) {
        int r = idx >> 4, u = idx & 15;
        int row = base + r;
        float4 v = make_float4(0.f, 0.f, 0.f, 0.f);
        if (row < N) v = *(const float4*)&x[(size_t)row * 64 + u * 4];
        *(float4*)&Xs[r * PX + ((u ^ ((r >> 2) & 7)) << 2)] = v;
    }
    __syncthreads();

    const float* Wh = Ws + half * 64 * PW;
    const float* bb = half ? b2 : b1;
    const float* gg = half ? g2 : g1;
    const float* ee = half ? be2 : be1;

    u64 acc[4][4];
    {
        u64 p0 = pk2(bb[c0 + 0], bb[c0 + 1]);
        u64 p1 = pk2(bb[c0 + 2], bb[c0 + 3]);
        u64 p2 = pk2(bb[c0 + 4], bb[c0 + 5]);
        u64 p3 = pk2(bb[c0 + 6], bb[c0 + 7]);
#pragma unroll
        for (int rr = 0; rr < 4; rr++) {
            acc[rr][0] = p0; acc[rr][1] = p1; acc[rr][2] = p2; acc[rr][3] = p3;
        }
    }

#pragma unroll
    for (int j0 = 0; j0 < 64; j0 += 4) {
        const int slot = ((j0 >> 2) ^ key) << 2;
        float4 xv[4];
#pragma unroll
        for (int rr = 0; rr < 4; rr++)
            xv[rr] = *(const float4*)&Xs[(r0 + rr) * PX + slot];
#pragma unroll
        for (int jj = 0; jj < 4; jj++) {
            double2 wa = *(const double2*)&Wh[(j0 + jj) * PW + ((cg & 7) << 2)];
            double2 wb = *(const double2*)&Wh[(j0 + jj) * PW + 32 + ((cg & 7) << 2)];
            u64 w0 = d2u(wa.x), w1 = d2u(wa.y);
            u64 w2_ = d2u(wb.x), w3 = d2u(wb.y);
#pragma unroll
            for (int rr = 0; rr < 4; rr++) {
                float xs_ = (jj == 0) ? xv[rr].x : (jj == 1) ? xv[rr].y
                          : (jj == 2) ? xv[rr].z : xv[rr].w;
                u64 xd = dup2(xs_);
                fma2(acc[rr][0], xd, w0);
                fma2(acc[rr][1], xd, w1);
                fma2(acc[rr][2], xd, w2_);
                fma2(acc[rr][3], xd, w3);
            }
        }
    }

    float4 ga = *(const float4*)&gg[c0], gb = *(const float4*)&gg[c0 + 4];
    float4 ea = *(const float4*)&ee[c0], eb = *(const float4*)&ee[c0 + 4];
#pragma unroll
    for (int rr = 0; rr < 4; rr++) {
        float2 v0 = up2(acc[rr][0]), v1 = up2(acc[rr][1]);
        float2 v2 = up2(acc[rr][2]), v3 = up2(acc[rr][3]);
        float s  = v0.x + v0.y + v1.x + v1.y + v2.x + v2.y + v3.x + v3.y;
        float s2 = v0.x*v0.x + v0.y*v0.y + v1.x*v1.x + v1.y*v1.y
                 + v2.x*v2.x + v2.y*v2.y + v3.x*v3.x + v3.y*v3.y;
#pragma unroll
        for (int o = 4; o > 0; o >>= 1) {
            s  += __shfl_xor_sync(0xffffffffu, s,  o);
            s2 += __shfl_xor_sync(0xffffffffu, s2, o);
        }
        float mu  = s * (1.f / 64.f);
        float var = s2 * (1.f / 64.f) - mu * mu;
        float inv = rsqrtf(var + 1e-5f);
        int row = base + r0 + rr;
        if (row < N) {
            float4 o0, o1;
            o0.x = fmaxf((v0.x - mu) * inv * ga.x + ea.x, 0.f);
            o0.y = fmaxf((v0.y - mu) * inv * ga.y + ea.y, 0.f);
            o0.z = fmaxf((v1.x - mu) * inv * ga.z + ea.z, 0.f);
            o0.w = fmaxf((v1.y - mu) * inv * ga.w + ea.w, 0.f);
            o1.x = fmaxf((v2.x - mu) * inv * gb.x + eb.x, 0.f);
            o1.y = fmaxf((v2.y - mu) * inv * gb.y + eb.y, 0.f);
            o1.z = fmaxf((v3.x - mu) * inv * gb.z + eb.z, 0.f);
            o1.w = fmaxf((v3.y - mu) * inv * gb.w + eb.w, 0.f);
            float* op = &out[(size_t)row * 256 + half * 64 + c0];
            *(float4*)op       = o0;
            *(float4*)(op + 4) = o1;
        }
    }
}

// ---------------------------------------------------------------------------
// blk1 (INC=256 final layer): y = relu(LN(x @ W + b)), outC = 64.
// ---------------------------------------------------------------------------
template <int INC>
__global__ __launch_bounds__(256)
void blk1_kernel(const float* __restrict__ x, int ldx,
                 const float* __restrict__ W,
                 const float* __restrict__ bias,
                 const float* __restrict__ gam,
                 const float* __restrict__ bet,
                 float* __restrict__ out, int ldo, int N)
{
    constexpr int KC = 64;
    constexpr int PX = 68;
    constexpr int PW = 68;
    constexpr int ROWS = 128;
    extern __shared__ float sm[];
    float* Xs = sm;
    float* Ws = sm + ROWS * PX;

    const int t   = threadIdx.x;
    const int cg  = t & 7;
    const int rg  = t >> 3;
    const int r0  = rg * 4;
    const int c0  = cg * 8;
    const int key = rg & 7;
    const int base = blockIdx.x * ROWS;

    u64 acc[4][4];
    {
        u64 b0 = pk2(bias[c0 + 0], bias[c0 + 1]);
        u64 b1 = pk2(bias[c0 + 2], bias[c0 + 3]);
        u64 b2 = pk2(bias[c0 + 4], bias[c0 + 5]);
        u64 b3 = pk2(bias[c0 + 6], bias[c0 + 7]);
#pragma unroll
        for (int rr = 0; rr < 4; rr++) {
            acc[rr][0] = b0; acc[rr][1] = b1; acc[rr][2] = b2; acc[rr][3] = b3;
        }
    }

    for (int k0 = 0; k0 < INC; k0 += KC) {
        __syncthreads();
        for (int idx = t; idx < KC * 16; idx += 256) {
            int j = idx >> 4, q = idx & 15;
            int pq = (q >> 1) + ((q & 1) << 3);
            *(float4*)&Ws[j * PW + pq * 4] =
                *(const float4*)&W[(size_t)(k0 + j) * 64 + q * 4];
        }
        for (int idx = t; idx < ROWS * 16; idx += 256) {
            int r = idx >> 4, u = idx & 15;
            int row = base + r;
            float4 v = make_float4(0.f, 0.f, 0.f, 0.f);
            if (row < N)
                v = *(const float4*)&x[(size_t)row * ldx + k0 + u * 4];
            *(float4*)&Xs[r * PX + ((u ^ ((r >> 2) & 7)) << 2)] = v;
        }
        __syncthreads();

#pragma unroll
        for (int j0 = 0; j0 < KC; j0 += 4) {
            const int slot = ((j0 >> 2) ^ key) << 2;
            float4 xv[4];
#pragma unroll
            for (int rr = 0; rr < 4; rr++)
                xv[rr] = *(const float4*)&Xs[(r0 + rr) * PX + slot];
#pragma unroll
            for (int jj = 0; jj < 4; jj++) {
                double2 wa = *(const double2*)&Ws[(j0 + jj) * PW + (cg << 2)];
                double2 wb = *(const double2*)&Ws[(j0 + jj) * PW + 32 + (cg << 2)];
                u64 w0 = d2u(wa.x), w1 = d2u(wa.y);
                u64 w2_ = d2u(wb.x), w3 = d2u(wb.y);
#pragma unroll
                for (int rr = 0; rr < 4; rr++) {
                    float xs_ = (jj == 0) ? xv[rr].x : (jj == 1) ? xv[rr].y
                              : (jj == 2) ? xv[rr].z : xv[rr].w;
                    u64 xd = dup2(xs_);
                    fma2(acc[rr][0], xd, w0);
                    fma2(acc[rr][1], xd, w1);
                    fma2(acc[rr][2], xd, w2_);
                    fma2(acc[rr][3], xd, w3);
                }
            }
        }
    }

    float4 g0 = *(const float4*)&gam[c0], g1 = *(const float4*)&gam[c0 + 4];
    float4 e0 = *(const float4*)&bet[c0], e1 = *(const float4*)&bet[c0 + 4];
#pragma unroll
    for (int rr = 0; rr < 4; rr++) {
        float2 v0 = up2(acc[rr][0]), v1 = up2(acc[rr][1]);
        float2 v2 = up2(acc[rr][2]), v3 = up2(acc[rr][3]);
        float s  = v0.x + v0.y + v1.x + v1.y + v2.x + v2.y + v3.x + v3.y;
        float s2 = v0.x*v0.x + v0.y*v0.y + v1.x*v1.x + v1.y*v1.y
                 + v2.x*v2.x + v2.y*v2.y + v3.x*v3.x + v3.y*v3.y;
#pragma unroll
        for (int o = 4; o > 0; o >>= 1) {
            s  += __shfl_xor_sync(0xffffffffu, s,  o);
            s2 += __shfl_xor_sync(0xffffffffu, s2, o);
        }
        float mu  = s * (1.f / 64.f);
        float var = s2 * (1.f / 64.f) - mu * mu;
        float inv = rsqrtf(var + 1e-5f);
        int row = base + r0 + rr;
        if (row < N) {
            float4 o0, o1;
            o0.x = fmaxf((v0.x - mu) * inv * g0.x + e0.x, 0.f);
            o0.y = fmaxf((v0.y - mu) * inv * g0.y + e0.y, 0.f);
            o0.z = fmaxf((v1.x - mu) * inv * g0.z + e0.z, 0.f);
            o0.w = fmaxf((v1.y - mu) * inv * g0.w + e0.w, 0.f);
            o1.x = fmaxf((v2.x - mu) * inv * g1.x + e1.x, 0.f);
            o1.y = fmaxf((v2.y - mu) * inv * g1.y + e1.y, 0.f);
            o1.z = fmaxf((v3.x - mu) * inv * g1.z + e1.z, 0.f);
            o1.w = fmaxf((v3.y - mu) * inv * g1.w + e1.w, 0.f);
            *(float4*)&out[(size_t)row * ldo + c0]     = o0;
            *(float4*)&out[(size_t)row * ldo + c0 + 4] = o1;
        }
    }
}

// ---------------------------------------------------------------------------
// Sparse submanifold conv. 256 rows/block, 256 threads.
// Sparse phase: warp-per-k-segment, W[k] column cached in 32 registers,
// x row broadcast LDG, accumulation via gmem RED (atomicAdd, result unused)
// into the block-private g_accum slice (zeroed by this block at staging).
// Dense self tap in registers (f32x2); merge + LN(32) + ReLU at the end.
// ---------------------------------------------------------------------------
template <int INC>
__global__ __launch_bounds__(256)
void conv_kernel(const float* __restrict__ x, int ldx,
                 const float* __restrict__ W,      // [27][INC][32]
                 const float* __restrict__ bias,
                 const float* __restrict__ gam,
                 const float* __restrict__ bet,
                 float* __restrict__ out, int ldo, int N)
{
    constexpr int ROWS = 256;
    constexpr int U    = INC / 4;
    extern __shared__ float sm[];
    float* Xs = sm;                 // [256][INC] swizzled
    float* Ws = Xs + ROWS * INC;    // [INC][32] self-tap W
    __shared__ int cnts[26];

    const int t    = threadIdx.x;
    const int lane = t & 31;
    const int wid  = t >> 5;
    const int base = blockIdx.x * ROWS;

    // zero this block's accum slice (ordered before REDs by __syncthreads)
    {
        float* ac = g_accum + (size_t)(base + t) * 32;
        float4 z = make_float4(0.f, 0.f, 0.f, 0.f);
#pragma unroll
        for (int i = 0; i < 8; i++) ((float4*)ac)[i] = z;
    }
    // stage own row into Xs (swizzled)
    {
        const int row  = base + t;
        const int skey = (t >> 2) & 7;
        const float4* xr = (const float4*)(x + (size_t)row * ldx);
#pragma unroll
        for (int u = 0; u < U; u++) {
            float4 v = make_float4(0.f, 0.f, 0.f, 0.f);
            if (row < N) v = __ldg(xr + u);
            *(float4*)&Xs[t * INC + ((u ^ skey) << 2)] = v;
        }
    }
    // stage self-tap W (k=13)
    {
        const float4* Wk4 = (const float4*)(W + (size_t)13 * INC * 32);
        for (int i = t; i < INC * 8; i += 256)
            ((float4*)Ws)[i] = __ldg(Wk4 + i);
    }
    if (t < 26) cnts[t] = g_cnt[blockIdx.x * 26 + t];
    __syncthreads();

    // ---- sparse phase: warp per k-segment, W cached in registers ----
    for (int s = wid; s < 26; s += 8) {
        const int n_e = cnts[s];
        if (n_e == 0) continue;
        const int k = s + (s >= 13);
        const int* ep = g_ent + ((size_t)blockIdx.x * 26 + s) * 256;
#pragma unroll
        for (int h = 0; h < INC / 32; h++) {
            float wreg[32];
            const float* Wk = W + ((size_t)k * INC + h * 32) * 32 + lane;
#pragma unroll
            for (int j = 0; j < 32; j++) wreg[j] = __ldg(Wk + j * 32);
            for (int e = 0; e < n_e; e++) {
                const int p   = __ldg(ep + e);
                const int row = p & 255;
                const int ni  = p >> 8;
                const float4* xr = (const float4*)(x + (size_t)ni * ldx + h * 32);
                float a = 0.f;
#pragma unroll
                for (int u = 0; u < 8; u++) {
                    float4 xq = __ldg(xr + u);        // warp-broadcast
                    a += xq.x * wreg[4*u + 0] + xq.y * wreg[4*u + 1]
                       + xq.z * wreg[4*u + 2] + xq.w * wreg[4*u + 3];
                }
                atomicAdd(&g_accum[(size_t)(base + row) * 32 + lane], a);  // RED
            }
        }
    }
    __threadfence();
    __syncthreads();

    // ---- dense self tap (k=13), register tiled: 4 rows x 8 ch ----
    const int cg  = t & 3;
    const int rg  = t >> 2;                  // 0..63
    const int r0  = rg * 4;
    const int c0  = cg * 8;
    const int key = rg & 7;

    u64 acc[4][4];
    {
        u64 b0 = pk2(bias[c0 + 0], bias[c0 + 1]);
        u64 b1 = pk2(bias[c0 + 2], bias[c0 + 3]);
        u64 b2 = pk2(bias[c0 + 4], bias[c0 + 5]);
        u64 b3 = pk2(bias[c0 + 6], bias[c0 + 7]);
#pragma unroll
        for (int rr = 0; rr < 4; rr++) {
            acc[rr][0] = b0; acc[rr][1] = b1; acc[rr][2] = b2; acc[rr][3] = b3;
        }
    }

#pragma unroll
    for (int j0 = 0; j0 < INC; j0 += 4) {
        const int slot = ((j0 >> 2) ^ key) << 2;
        float4 xv[4];
#pragma unroll
        for (int rr = 0; rr < 4; rr++)
            xv[rr] = *(const float4*)&Xs[(r0 + rr) * INC + slot];
#pragma unroll
        for (int jj = 0; jj < 4; jj++) {
            double2 wa = *(const double2*)&Ws[(j0 + jj) * 32 + c0];
            double2 wb = *(const double2*)&Ws[(j0 + jj) * 32 + c0 + 4];
            u64 w0 = d2u(wa.x), w1 = d2u(wa.y);
            u64 w2_ = d2u(wb.x), w3 = d2u(wb.y);
#pragma unroll
            for (int rr = 0; rr < 4; rr++) {
                float xs_ = (jj == 0) ? xv[rr].x : (jj == 1) ? xv[rr].y
                          : (jj == 2) ? xv[rr].z : xv[rr].w;
                u64 xd = dup2(xs_);
                fma2(acc[rr][0], xd, w0);
                fma2(acc[rr][1], xd, w1);
                fma2(acc[rr][2], xd, w2_);
                fma2(acc[rr][3], xd, w3);
            }
        }
    }

    // ---- merge + LN(32) + ReLU + store ----
    float4 g0 = *(const float4*)&gam[c0], g1 = *(const float4*)&gam[c0 + 4];
    float4 e0 = *(const float4*)&bet[c0], e1 = *(const float4*)&bet[c0 + 4];
#pragma unroll
    for (int rr = 0; rr < 4; rr++) {
        const int row = r0 + rr;
        const double2 ap0 = *(const double2*)(g_accum + (size_t)(base + row) * 32 + c0);
        const double2 ap1 = *(const double2*)(g_accum + (size_t)(base + row) * 32 + c0 + 4);
        u64 a0 = addp(acc[rr][0], d2u(ap0.x));
        u64 a1 = addp(acc[rr][1], d2u(ap0.y));
        u64 a2 = addp(acc[rr][2], d2u(ap1.x));
        u64 a3 = addp(acc[rr][3], d2u(ap1.y));
        float2 v0 = up2(a0), v1 = up2(a1), v2 = up2(a2), v3 = up2(a3);
        float s  = v0.x + v0.y + v1.x + v1.y + v2.x + v2.y + v3.x + v3.y;
        float s2 = v0.x*v0.x + v0.y*v0.y + v1.x*v1.x + v1.y*v1.y
                 + v2.x*v2.x + v2.y*v2.y + v3.x*v3.x + v3.y*v3.y;
#pragma unroll
        for (int o = 2; o > 0; o >>= 1) {
            s  += __shfl_xor_sync(0xffffffffu, s,  o);
            s2 += __shfl_xor_sync(0xffffffffu, s2, o);
        }
        float mu  = s * (1.f / 32.f);
        float var = s2 * (1.f / 32.f) - mu * mu;
        float inv = rsqrtf(var + 1e-5f);
        int grow = base + row;
        if (grow < N) {
            float4 o0, o1;
            o0.x = fmaxf((v0.x - mu) * inv * g0.x + e0.x, 0.f);
            o0.y = fmaxf((v0.y - mu) * inv * g0.y + e0.y, 0.f);
            o0.z = fmaxf((v1.x - mu) * inv * g0.z + e0.z, 0.f);
            o0.w = fmaxf((v1.y - mu) * inv * g0.w + e0.w, 0.f);
            o1.x = fmaxf((v2.x - mu) * inv * g1.x + e1.x, 0.f);
            o1.y = fmaxf((v2.y - mu) * inv * g1.y + e1.y, 0.f);
            o1.z = fmaxf((v3.x - mu) * inv * g1.z + e1.z, 0.f);
            o1.w = fmaxf((v3.y - mu) * inv * g1.w + e1.w, 0.f);
            *(float4*)&out[(size_t)grow * ldo + c0]     = o0;
            *(float4*)&out[(size_t)grow * ldo + c0 + 4] = o1;
        }
    }
}

// ---------------------------------------------------------------------------
extern "C" void kernel_launch(void* const* d_in, const int* in_sizes, int n_in,
                              void* d_out, int out_size)
{
    const float* vox = (const float*)d_in[0];
    const int*   nbr = (const int*)d_in[1];
    const float* W1  = (const float*)d_in[2];
    const float* b1  = (const float*)d_in[3];
    const float* g1  = (const float*)d_in[4];
    const float* be1 = (const float*)d_in[5];
    const float* W2  = (const float*)d_in[6];
    const float* b2  = (const float*)d_in[7];
    const float* g2  = (const float*)d_in[8];
    const float* be2 = (const float*)d_in[9];
    const float* W3  = (const float*)d_in[10];
    const float* b3  = (const float*)d_in[11];
    const float* g3  = (const float*)d_in[12];
    const float* be3 = (const float*)d_in[13];
    const float* W4  = (const float*)d_in[14];
    const float* b4  = (const float*)d_in[15];
    const float* g4  = (const float*)d_in[16];
    const float* be4 = (const float*)d_in[17];
    const float* W5  = (const float*)d_in[18];
    const float* b5  = (const float*)d_in[19];
    const float* g5  = (const float*)d_in[20];
    const float* be5 = (const float*)d_in[21];
    const float* W6  = (const float*)d_in[22];
    const float* b6  = (const float*)d_in[23];
    const float* g6  = (const float*)d_in[24];
    const float* be6 = (const float*)d_in[25];
    const float* W7  = (const float*)d_in[26];
    const float* b7  = (const float*)d_in[27];
    const float* g7  = (const float*)d_in[28];
    const float* be7 = (const float*)d_in[29];

    const int N = in_sizes[0] / 64;

    float* cat = nullptr;
    cudaGetSymbolAddress((void**)&cat, g_cat);

    const int nbd  = (N + 63) / 64;
    const int nbc  = (N + 255) / 256;
    const int nbf  = (N + 127) / 128;

    const int smem_dual = (64 * 68 + 2 * 64 * 68) * 4;        // 52,224
    const int smem_f    = (128 * 68 + 64 * 68) * 4;           // 52,224
    const int smem_c64  = (256 * 64 + 64 * 32) * 4;           // 73,728
    const int smem_c32  = (256 * 32 + 32 * 32) * 4;           // 36,864
    cudaFuncSetAttribute(blk1_dual_kernel,
                         cudaFuncAttributeMaxDynamicSharedMemorySize, smem_dual);
    cudaFuncSetAttribute(blk1_kernel<256>,
                         cudaFuncAttributeMaxDynamicSharedMemorySize, smem_f);
    cudaFuncSetAttribute(conv_kernel<64>,
                         cudaFuncAttributeMaxDynamicSharedMemorySize, smem_c64);
    cudaFuncSetAttribute(conv_kernel<32>,
                         cudaFuncAttributeMaxDynamicSharedMemorySize, smem_c32);

    // entry list: built once, reused by all 4 convs
    build_list_kernel<<<nbc, 256>>>(nbr, N);
    // f1 | f2 fused
    blk1_dual_kernel<<<nbd, 256, smem_dual>>>(vox, W1, b1, g1, be1,
                                              W2, b2, g2, be2, cat, N);
    // f3..f6 (sparse submanifold convs, chained)
    conv_kernel<64><<<nbc, 256, smem_c64>>>(cat + 64,  256, W3, b3, g3, be3, cat + 128, 256, N);
    conv_kernel<32><<<nbc, 256, smem_c32>>>(cat + 128, 256, W4, b4, g4, be4, cat + 160, 256, N);
    conv_kernel<32><<<nbc, 256, smem_c32>>>(cat + 160, 256, W5, b5, g5, be5, cat + 192, 256, N);
    conv_kernel<32><<<nbc, 256, smem_c32>>>(cat + 192, 256, W6, b6, g6, be6, cat + 224, 256, N);
    // final: blk1 over concat(256) -> out(64)
    blk1_kernel<256><<<nbf, 256, smem_f>>>(cat, 256, W7, b7, g7, be7,
                                           (float*)d_out, 64, N);
}

// round 12
// speedup vs baseline: 1.1455x; 1.1455x over previous
#include <cuda_runtime.h>

#define MAX_N 262144
#define MAX_BLK (MAX_N / 256)
__device__ float g_cat[(size_t)MAX_N * 256];
__device__ float g_accum[(size_t)MAX_N * 32];
__device__ int   g_ent[(size_t)MAX_BLK * 26 * 256];
__device__ int   g_cnt[(size_t)MAX_BLK * 26];

typedef unsigned long long u64;

__device__ __forceinline__ u64 pk2(float a, float b) {
    u64 r;
    asm("mov.b64 %0, {%1, %2};" : "=l"(r)
        : "r"(__float_as_uint(a)), "r"(__float_as_uint(b)));
    return r;
}
__device__ __forceinline__ u64 dup2(float a) {
    u64 r; unsigned ai = __float_as_uint(a);
    asm("mov.b64 %0, {%1, %1};" : "=l"(r) : "r"(ai));
    return r;
}
__device__ __forceinline__ float2 up2(u64 v) {
    unsigned a, b;
    asm("mov.b64 {%0, %1}, %2;" : "=r"(a), "=r"(b) : "l"(v));
    return make_float2(__uint_as_float(a), __uint_as_float(b));
}
__device__ __forceinline__ void fma2(u64& d, u64 a, u64 b) {
    asm("fma.rn.f32x2 %0, %1, %2, %0;" : "+l"(d) : "l"(a), "l"(b));
}
__device__ __forceinline__ u64 addp(u64 a, u64 b) {
    u64 r;
    asm("add.rn.f32x2 %0, %1, %2;" : "=l"(r) : "l"(a), "l"(b));
    return r;
}
__device__ __forceinline__ u64 d2u(double d) { return __double_as_longlong(d); }

// ---------------------------------------------------------------------------
// build_list: one pass over nbr, compact valid non-self taps into per-(block,k)
// segments. Reused by all 4 conv layers. Entry = (ni << 8) | local_row.
// ---------------------------------------------------------------------------
__global__ __launch_bounds__(256)
void build_list_kernel(const int* __restrict__ nbr, int N)
{
    __shared__ int snb[256 * 27];
    __shared__ int cnt[26];

    const int t    = threadIdx.x;
    const int lane = t & 31;
    const int base = blockIdx.x * 256;

    if (t < 26) cnt[t] = 0;
    for (int i = t; i < 256 * 27; i += 256) {
        long long g = (long long)base * 27 + i;
        int v = -1;
        if (g < (long long)N * 27) v = __ldg(&nbr[g]);
        snb[i] = v;
    }
    __syncthreads();

#pragma unroll
    for (int k = 0; k < 27; k++) {
        if (k == 13) continue;
        const int s  = k - (k > 13);
        const int nb = snb[t * 27 + k];
        const bool valid = nb >= 0;
        unsigned m = __ballot_sync(0xffffffffu, valid);
        if (m) {
            int leader = __ffs(m) - 1;
            int wb = 0;
            if (lane == leader) wb = atomicAdd(&cnt[s], __popc(m));
            wb = __shfl_sync(0xffffffffu, wb, leader);
            if (valid) {
                int pos = wb + __popc(m & ((1u << lane) - 1));
                g_ent[((size_t)blockIdx.x * 26 + s) * 256 + pos] = (nb << 8) | t;
            }
        }
    }
    __syncthreads();
    if (t < 26) g_cnt[blockIdx.x * 26 + t] = cnt[t];
}

// ---------------------------------------------------------------------------
// blk1_dual: f1 = relu(LN(x@W1+b1)), f2 = relu(LN(x@W2+b2)) in one pass.
// ---------------------------------------------------------------------------
__global__ __launch_bounds__(256)
void blk1_dual_kernel(const float* __restrict__ x,
                      const float* __restrict__ W1, const float* __restrict__ b1,
                      const float* __restrict__ g1, const float* __restrict__ be1,
                      const float* __restrict__ W2, const float* __restrict__ b2,
                      const float* __restrict__ g2, const float* __restrict__ be2,
                      float* __restrict__ out, int N)
{
    constexpr int ROWS = 64, PX = 68, PW = 68;
    extern __shared__ float sm[];
    float* Xs = sm;
    float* Ws = sm + ROWS * PX;

    const int t    = threadIdx.x;
    const int cg   = t & 15;
    const int rg   = t >> 4;
    const int r0   = rg * 4;
    const int half = cg >> 3;
    const int c0   = (cg & 7) * 8;
    const int key  = rg & 7;
    const int base = blockIdx.x * ROWS;

    for (int idx = t; idx < 64 * 16; idx += 256) {
        int j = idx >> 4, q = idx & 15;
        int pq = (q >> 1) + ((q & 1) << 3);
        *(float4*)&Ws[j * PW + pq * 4]            = *(const float4*)&W1[j * 64 + q * 4];
        *(float4*)&Ws[64 * PW + j * PW + pq * 4]  = *(const float4*)&W2[j * 64 + q * 4];
    }
    for (int idx = t; idx < ROWS * 16; idx += 256) {
        int r = idx >> 4, u = idx & 15;
        int row = base + r;
        float4 v = make_float4(0.f, 0.f, 0.f, 0.f);
        if (row < N) v = *(const float4*)&x[(size_t)row * 64 + u * 4];
        *(float4*)&Xs[r * PX + ((u ^ ((r >> 2) & 7)) << 2)] = v;
    }
    __syncthreads();

    const float* Wh = Ws + half * 64 * PW;
    const float* bb = half ? b2 : b1;
    const float* gg = half ? g2 : g1;
    const float* ee = half ? be2 : be1;

    u64 acc[4][4];
    {
        u64 p0 = pk2(bb[c0 + 0], bb[c0 + 1]);
        u64 p1 = pk2(bb[c0 + 2], bb[c0 + 3]);
        u64 p2 = pk2(bb[c0 + 4], bb[c0 + 5]);
        u64 p3 = pk2(bb[c0 + 6], bb[c0 + 7]);
#pragma unroll
        for (int rr = 0; rr < 4; rr++) {
            acc[rr][0] = p0; acc[rr][1] = p1; acc[rr][2] = p2; acc[rr][3] = p3;
        }
    }

#pragma unroll
    for (int j0 = 0; j0 < 64; j0 += 4) {
        const int slot = ((j0 >> 2) ^ key) << 2;
        float4 xv[4];
#pragma unroll
        for (int rr = 0; rr < 4; rr++)
            xv[rr] = *(const float4*)&Xs[(r0 + rr) * PX + slot];
#pragma unroll
        for (int jj = 0; jj < 4; jj++) {
            double2 wa = *(const double2*)&Wh[(j0 + jj) * PW + ((cg & 7) << 2)];
            double2 wb = *(const double2*)&Wh[(j0 + jj) * PW + 32 + ((cg & 7) << 2)];
            u64 w0 = d2u(wa.x), w1 = d2u(wa.y);
            u64 w2_ = d2u(wb.x), w3 = d2u(wb.y);
#pragma unroll
            for (int rr = 0; rr < 4; rr++) {
                float xs_ = (jj == 0) ? xv[rr].x : (jj == 1) ? xv[rr].y
                          : (jj == 2) ? xv[rr].z : xv[rr].w;
                u64 xd = dup2(xs_);
                fma2(acc[rr][0], xd, w0);
                fma2(acc[rr][1], xd, w1);
                fma2(acc[rr][2], xd, w2_);
                fma2(acc[rr][3], xd, w3);
            }
        }
    }

    float4 ga = *(const float4*)&gg[c0], gb = *(const float4*)&gg[c0 + 4];
    float4 ea = *(const float4*)&ee[c0], eb = *(const float4*)&ee[c0 + 4];
#pragma unroll
    for (int rr = 0; rr < 4; rr++) {
        float2 v0 = up2(acc[rr][0]), v1 = up2(acc[rr][1]);
        float2 v2 = up2(acc[rr][2]), v3 = up2(acc[rr][3]);
        float s  = v0.x + v0.y + v1.x + v1.y + v2.x + v2.y + v3.x + v3.y;
        float s2 = v0.x*v0.x + v0.y*v0.y + v1.x*v1.x + v1.y*v1.y
                 + v2.x*v2.x + v2.y*v2.y + v3.x*v3.x + v3.y*v3.y;
#pragma unroll
        for (int o = 4; o > 0; o >>= 1) {
            s  += __shfl_xor_sync(0xffffffffu, s,  o);
            s2 += __shfl_xor_sync(0xffffffffu, s2, o);
        }
        float mu  = s * (1.f / 64.f);
        float var = s2 * (1.f / 64.f) - mu * mu;
        float inv = rsqrtf(var + 1e-5f);
        int row = base + r0 + rr;
        if (row < N) {
            float4 o0, o1;
            o0.x = fmaxf((v0.x - mu) * inv * ga.x + ea.x, 0.f);
            o0.y = fmaxf((v0.y - mu) * inv * ga.y + ea.y, 0.f);
            o0.z = fmaxf((v1.x - mu) * inv * ga.z + ea.z, 0.f);
            o0.w = fmaxf((v1.y - mu) * inv * ga.w + ea.w, 0.f);
            o1.x = fmaxf((v2.x - mu) * inv * gb.x + eb.x, 0.f);
            o1.y = fmaxf((v2.y - mu) * inv * gb.y + eb.y, 0.f);
            o1.z = fmaxf((v3.x - mu) * inv * gb.z + eb.z, 0.f);
            o1.w = fmaxf((v3.y - mu) * inv * gb.w + eb.w, 0.f);
            float* op = &out[(size_t)row * 256 + half * 64 + c0];
            *(float4*)op       = o0;
            *(float4*)(op + 4) = o1;
        }
    }
}

// ---------------------------------------------------------------------------
// blk1 (INC=256 final layer): y = relu(LN(x @ W + b)), outC = 64.
// ---------------------------------------------------------------------------
template <int INC>
__global__ __launch_bounds__(256)
void blk1_kernel(const float* __restrict__ x, int ldx,
                 const float* __restrict__ W,
                 const float* __restrict__ bias,
                 const float* __restrict__ gam,
                 const float* __restrict__ bet,
                 float* __restrict__ out, int ldo, int N)
{
    constexpr int KC = 64;
    constexpr int PX = 68;
    constexpr int PW = 68;
    constexpr int ROWS = 128;
    extern __shared__ float sm[];
    float* Xs = sm;
    float* Ws = sm + ROWS * PX;

    const int t   = threadIdx.x;
    const int cg  = t & 7;
    const int rg  = t >> 3;
    const int r0  = rg * 4;
    const int c0  = cg * 8;
    const int key = rg & 7;
    const int base = blockIdx.x * ROWS;

    u64 acc[4][4];
    {
        u64 b0 = pk2(bias[c0 + 0], bias[c0 + 1]);
        u64 b1 = pk2(bias[c0 + 2], bias[c0 + 3]);
        u64 b2 = pk2(bias[c0 + 4], bias[c0 + 5]);
        u64 b3 = pk2(bias[c0 + 6], bias[c0 + 7]);
#pragma unroll
        for (int rr = 0; rr < 4; rr++) {
            acc[rr][0] = b0; acc[rr][1] = b1; acc[rr][2] = b2; acc[rr][3] = b3;
        }
    }

    for (int k0 = 0; k0 < INC; k0 += KC) {
        __syncthreads();
        for (int idx = t; idx < KC * 16; idx += 256) {
            int j = idx >> 4, q = idx & 15;
            int pq = (q >> 1) + ((q & 1) << 3);
            *(float4*)&Ws[j * PW + pq * 4] =
                *(const float4*)&W[(size_t)(k0 + j) * 64 + q * 4];
        }
        for (int idx = t; idx < ROWS * 16; idx += 256) {
            int r = idx >> 4, u = idx & 15;
            int row = base + r;
            float4 v = make_float4(0.f, 0.f, 0.f, 0.f);
            if (row < N)
                v = *(const float4*)&x[(size_t)row * ldx + k0 + u * 4];
            *(float4*)&Xs[r * PX + ((u ^ ((r >> 2) & 7)) << 2)] = v;
        }
        __syncthreads();

#pragma unroll
        for (int j0 = 0; j0 < KC; j0 += 4) {
            const int slot = ((j0 >> 2) ^ key) << 2;
            float4 xv[4];
#pragma unroll
            for (int rr = 0; rr < 4; rr++)
                xv[rr] = *(const float4*)&Xs[(r0 + rr) * PX + slot];
#pragma unroll
            for (int jj = 0; jj < 4; jj++) {
                double2 wa = *(const double2*)&Ws[(j0 + jj) * PW + (cg << 2)];
                double2 wb = *(const double2*)&Ws[(j0 + jj) * PW + 32 + (cg << 2)];
                u64 w0 = d2u(wa.x), w1 = d2u(wa.y);
                u64 w2_ = d2u(wb.x), w3 = d2u(wb.y);
#pragma unroll
                for (int rr = 0; rr < 4; rr++) {
                    float xs_ = (jj == 0) ? xv[rr].x : (jj == 1) ? xv[rr].y
                              : (jj == 2) ? xv[rr].z : xv[rr].w;
                    u64 xd = dup2(xs_);
                    fma2(acc[rr][0], xd, w0);
                    fma2(acc[rr][1], xd, w1);
                    fma2(acc[rr][2], xd, w2_);
                    fma2(acc[rr][3], xd, w3);
                }
            }
        }
    }

    float4 g0 = *(const float4*)&gam[c0], g1 = *(const float4*)&gam[c0 + 4];
    float4 e0 = *(const float4*)&bet[c0], e1 = *(const float4*)&bet[c0 + 4];
#pragma unroll
    for (int rr = 0; rr < 4; rr++) {
        float2 v0 = up2(acc[rr][0]), v1 = up2(acc[rr][1]);
        float2 v2 = up2(acc[rr][2]), v3 = up2(acc[rr][3]);
        float s  = v0.x + v0.y + v1.x + v1.y + v2.x + v2.y + v3.x + v3.y;
        float s2 = v0.x*v0.x + v0.y*v0.y + v1.x*v1.x + v1.y*v1.y
                 + v2.x*v2.x + v2.y*v2.y + v3.x*v3.x + v3.y*v3.y;
#pragma unroll
        for (int o = 4; o > 0; o >>= 1) {
            s  += __shfl_xor_sync(0xffffffffu, s,  o);
            s2 += __shfl_xor_sync(0xffffffffu, s2, o);
        }
        float mu  = s * (1.f / 64.f);
        float var = s2 * (1.f / 64.f) - mu * mu;
        float inv = rsqrtf(var + 1e-5f);
        int row = base + r0 + rr;
        if (row < N) {
            float4 o0, o1;
            o0.x = fmaxf((v0.x - mu) * inv * g0.x + e0.x, 0.f);
            o0.y = fmaxf((v0.y - mu) * inv * g0.y + e0.y, 0.f);
            o0.z = fmaxf((v1.x - mu) * inv * g0.z + e0.z, 0.f);
            o0.w = fmaxf((v1.y - mu) * inv * g0.w + e0.w, 0.f);
            o1.x = fmaxf((v2.x - mu) * inv * g1.x + e1.x, 0.f);
            o1.y = fmaxf((v2.y - mu) * inv * g1.y + e1.y, 0.f);
            o1.z = fmaxf((v3.x - mu) * inv * g1.z + e1.z, 0.f);
            o1.w = fmaxf((v3.y - mu) * inv * g1.w + e1.w, 0.f);
            *(float4*)&out[(size_t)row * ldo + c0]     = o0;
            *(float4*)&out[(size_t)row * ldo + c0 + 4] = o1;
        }
    }
}

// ---------------------------------------------------------------------------
// Sparse submanifold conv. 256 rows/block, 256 threads.
// Entry list staged in smem (kills the 250-cyc per-entry list-load chain).
// Work item = (segment, j-chunk of 16): warp caches 16 W values in regs,
// walks the segment's entries 2 at a time (8 LDG.128 in flight), REDs into
// block-private g_accum. Merge loads hoisted above the dense self-tap.
// ---------------------------------------------------------------------------
template <int INC>
__global__ __launch_bounds__(256)
void conv_kernel(const float* __restrict__ x, int ldx,
                 const float* __restrict__ W,      // [27][INC][32]
                 const float* __restrict__ bias,
                 const float* __restrict__ gam,
                 const float* __restrict__ bet,
                 float* __restrict__ out, int ldo, int N)
{
    constexpr int ROWS = 256;
    constexpr int U    = INC / 4;
    constexpr int NCH  = INC / 16;     // j-chunks per entry
    constexpr int SCAP = 32;           // smem entries per segment
    extern __shared__ float sm[];
    float* Xs = sm;                    // [256][INC] swizzled
    float* Ws = Xs + ROWS * INC;       // [INC][32] self-tap W
    int* se   = (int*)(Ws + INC * 32); // [26][SCAP] staged entries
    __shared__ int cnts[26];

    const int t    = threadIdx.x;
    const int lane = t & 31;
    const int wid  = t >> 5;
    const int base = blockIdx.x * ROWS;

    // zero this block's accum slice
    {
        float* ac = g_accum + (size_t)(base + t) * 32;
        float4 z = make_float4(0.f, 0.f, 0.f, 0.f);
#pragma unroll
        for (int i = 0; i < 8; i++) ((float4*)ac)[i] = z;
    }
    // stage own row into Xs (swizzled)
    {
        const int row  = base + t;
        const int skey = (t >> 2) & 7;
        const float4* xr = (const float4*)(x + (size_t)row * ldx);
#pragma unroll
        for (int u = 0; u < U; u++) {
            float4 v = make_float4(0.f, 0.f, 0.f, 0.f);
            if (row < N) v = __ldg(xr + u);
            *(float4*)&Xs[t * INC + ((u ^ skey) << 2)] = v;
        }
    }
    // stage self-tap W (k=13)
    {
        const float4* Wk4 = (const float4*)(W + (size_t)13 * INC * 32);
        for (int i = t; i < INC * 8; i += 256)
            ((float4*)Ws)[i] = __ldg(Wk4 + i);
    }
    // stage entry list head (unconditional; slots beyond count unused)
    for (int i = t; i < 26 * SCAP; i += 256) {
        int s = i >> 5, e = i & (SCAP - 1);
        se[i] = __ldg(&g_ent[((size_t)blockIdx.x * 26 + s) * 256 + e]);
    }
    if (t < 26) cnts[t] = g_cnt[blockIdx.x * 26 + t];
    __syncthreads();

    // ---- sparse phase: warp per (segment, j-chunk) ----
    for (int it = wid; it < 26 * NCH; it += 8) {
        const int s = it % 26;
        const int h = it / 26;
        const int n_e = cnts[s];
        if (n_e == 0) continue;
        const int k = s + (s >= 13);
        float wreg[16];
        const float* Wk = W + ((size_t)k * INC + h * 16) * 32 + lane;
#pragma unroll
        for (int j = 0; j < 16; j++) wreg[j] = __ldg(Wk + j * 32);
        const int* eps = se + s * SCAP;
        const int* epg = g_ent + ((size_t)blockIdx.x * 26 + s) * 256;
        int e = 0;
        for (; e + 2 <= n_e; e += 2) {
            const int p0 = (e     < SCAP) ? eps[e]     : __ldg(epg + e);
            const int p1 = (e + 1 < SCAP) ? eps[e + 1] : __ldg(epg + e + 1);
            const float4* xr0 = (const float4*)(x + (size_t)(p0 >> 8) * ldx + h * 16);
            const float4* xr1 = (const float4*)(x + (size_t)(p1 >> 8) * ldx + h * 16);
            float4 a0 = __ldg(xr0 + 0), a1 = __ldg(xr0 + 1);
            float4 a2 = __ldg(xr0 + 2), a3 = __ldg(xr0 + 3);
            float4 b0 = __ldg(xr1 + 0), b1 = __ldg(xr1 + 1);
            float4 b2 = __ldg(xr1 + 2), b3 = __ldg(xr1 + 3);
            float va = a0.x*wreg[0]  + a0.y*wreg[1]  + a0.z*wreg[2]  + a0.w*wreg[3]
                     + a1.x*wreg[4]  + a1.y*wreg[5]  + a1.z*wreg[6]  + a1.w*wreg[7]
                     + a2.x*wreg[8]  + a2.y*wreg[9]  + a2.z*wreg[10] + a2.w*wreg[11]
                     + a3.x*wreg[12] + a3.y*wreg[13] + a3.z*wreg[14] + a3.w*wreg[15];
            float vb = b0.x*wreg[0]  + b0.y*wreg[1]  + b0.z*wreg[2]  + b0.w*wreg[3]
                     + b1.x*wreg[4]  + b1.y*wreg[5]  + b1.z*wreg[6]  + b1.w*wreg[7]
                     + b2.x*wreg[8]  + b2.y*wreg[9]  + b2.z*wreg[10] + b2.w*wreg[11]
                     + b3.x*wreg[12] + b3.y*wreg[13] + b3.z*wreg[14] + b3.w*wreg[15];
            atomicAdd(&g_accum[(size_t)(base + (p0 & 255)) * 32 + lane], va);
            atomicAdd(&g_accum[(size_t)(base + (p1 & 255)) * 32 + lane], vb);
        }
        if (e < n_e) {
            const int p0 = (e < SCAP) ? eps[e] : __ldg(epg + e);
            const float4* xr0 = (const float4*)(x + (size_t)(p0 >> 8) * ldx + h * 16);
            float4 a0 = __ldg(xr0 + 0), a1 = __ldg(xr0 + 1);
            float4 a2 = __ldg(xr0 + 2), a3 = __ldg(xr0 + 3);
            float va = a0.x*wreg[0]  + a0.y*wreg[1]  + a0.z*wreg[2]  + a0.w*wreg[3]
                     + a1.x*wreg[4]  + a1.y*wreg[5]  + a1.z*wreg[6]  + a1.w*wreg[7]
                     + a2.x*wreg[8]  + a2.y*wreg[9]  + a2.z*wreg[10] + a2.w*wreg[11]
                     + a3.x*wreg[12] + a3.y*wreg[13] + a3.z*wreg[14] + a3.w*wreg[15];
            atomicAdd(&g_accum[(size_t)(base + (p0 & 255)) * 32 + lane], va);
        }
    }
    __threadfence();
    __syncthreads();

    // ---- hoist merge loads (L2 latency hides under dense compute) ----
    const int cg  = t & 3;
    const int rg  = t >> 2;                  // 0..63
    const int r0  = rg * 4;
    const int c0  = cg * 8;
    const int key = rg & 7;

    u64 hp[4][4];
#pragma unroll
    for (int rr = 0; rr < 4; rr++) {
        const double2* ap = (const double2*)(g_accum + (size_t)(base + r0 + rr) * 32 + c0);
        double2 q0 = ap[0], q1 = ap[1];
        hp[rr][0] = d2u(q0.x); hp[rr][1] = d2u(q0.y);
        hp[rr][2] = d2u(q1.x); hp[rr][3] = d2u(q1.y);
    }

    // ---- dense self tap (k=13), register tiled: 4 rows x 8 ch ----
    u64 acc[4][4];
    {
        u64 b0 = pk2(bias[c0 + 0], bias[c0 + 1]);
        u64 b1 = pk2(bias[c0 + 2], bias[c0 + 3]);
        u64 b2 = pk2(bias[c0 + 4], bias[c0 + 5]);
        u64 b3 = pk2(bias[c0 + 6], bias[c0 + 7]);
#pragma unroll
        for (int rr = 0; rr < 4; rr++) {
            acc[rr][0] = b0; acc[rr][1] = b1; acc[rr][2] = b2; acc[rr][3] = b3;
        }
    }

#pragma unroll
    for (int j0 = 0; j0 < INC; j0 += 4) {
        const int slot = ((j0 >> 2) ^ key) << 2;
        float4 xv[4];
#pragma unroll
        for (int rr = 0; rr < 4; rr++)
            xv[rr] = *(const float4*)&Xs[(r0 + rr) * INC + slot];
#pragma unroll
        for (int jj = 0; jj < 4; jj++) {
            double2 wa = *(const double2*)&Ws[(j0 + jj) * 32 + c0];
            double2 wb = *(const double2*)&Ws[(j0 + jj) * 32 + c0 + 4];
            u64 w0 = d2u(wa.x), w1 = d2u(wa.y);
            u64 w2_ = d2u(wb.x), w3 = d2u(wb.y);
#pragma unroll
            for (int rr = 0; rr < 4; rr++) {
                float xs_ = (jj == 0) ? xv[rr].x : (jj == 1) ? xv[rr].y
                          : (jj == 2) ? xv[rr].z : xv[rr].w;
                u64 xd = dup2(xs_);
                fma2(acc[rr][0], xd, w0);
                fma2(acc[rr][1], xd, w1);
                fma2(acc[rr][2], xd, w2_);
                fma2(acc[rr][3], xd, w3);
            }
        }
    }

    // ---- merge + LN(32) + ReLU + store ----
    float4 g0 = *(const float4*)&gam[c0], g1 = *(const float4*)&gam[c0 + 4];
    float4 e0 = *(const float4*)&bet[c0], e1 = *(const float4*)&bet[c0 + 4];
#pragma unroll
    for (int rr = 0; rr < 4; rr++) {
        u64 a0 = addp(acc[rr][0], hp[rr][0]);
        u64 a1 = addp(acc[rr][1], hp[rr][1]);
        u64 a2 = addp(acc[rr][2], hp[rr][2]);
        u64 a3 = addp(acc[rr][3], hp[rr][3]);
        float2 v0 = up2(a0), v1 = up2(a1), v2 = up2(a2), v3 = up2(a3);
        float s  = v0.x + v0.y + v1.x + v1.y + v2.x + v2.y + v3.x + v3.y;
        float s2 = v0.x*v0.x + v0.y*v0.y + v1.x*v1.x + v1.y*v1.y
                 + v2.x*v2.x + v2.y*v2.y + v3.x*v3.x + v3.y*v3.y;
#pragma unroll
        for (int o = 2; o > 0; o >>= 1) {
            s  += __shfl_xor_sync(0xffffffffu, s,  o);
            s2 += __shfl_xor_sync(0xffffffffu, s2, o);
        }
        float mu  = s * (1.f / 32.f);
        float var = s2 * (1.f / 32.f) - mu * mu;
        float inv = rsqrtf(var + 1e-5f);
        int grow = base + r0 + rr;
        if (grow < N) {
            float4 o0, o1;
            o0.x = fmaxf((v0.x - mu) * inv * g0.x + e0.x, 0.f);
            o0.y = fmaxf((v0.y - mu) * inv * g0.y + e0.y, 0.f);
            o0.z = fmaxf((v1.x - mu) * inv * g0.z + e0.z, 0.f);
            o0.w = fmaxf((v1.y - mu) * inv * g0.w + e0.w, 0.f);
            o1.x = fmaxf((v2.x - mu) * inv * g1.x + e1.x, 0.f);
            o1.y = fmaxf((v2.y - mu) * inv * g1.y + e1.y, 0.f);
            o1.z = fmaxf((v3.x - mu) * inv * g1.z + e1.z, 0.f);
            o1.w = fmaxf((v3.y - mu) * inv * g1.w + e1.w, 0.f);
            *(float4*)&out[(size_t)grow * ldo + c0]     = o0;
            *(float4*)&out[(size_t)grow * ldo + c0 + 4] = o1;
        }
    }
}

// ---------------------------------------------------------------------------
extern "C" void kernel_launch(void* const* d_in, const int* in_sizes, int n_in,
                              void* d_out, int out_size)
{
    const float* vox = (const float*)d_in[0];
    const int*   nbr = (const int*)d_in[1];
    const float* W1  = (const float*)d_in[2];
    const float* b1  = (const float*)d_in[3];
    const float* g1  = (const float*)d_in[4];
    const float* be1 = (const float*)d_in[5];
    const float* W2  = (const float*)d_in[6];
    const float* b2  = (const float*)d_in[7];
    const float* g2  = (const float*)d_in[8];
    const float* be2 = (const float*)d_in[9];
    const float* W3  = (const float*)d_in[10];
    const float* b3  = (const float*)d_in[11];
    const float* g3  = (const float*)d_in[12];
    const float* be3 = (const float*)d_in[13];
    const float* W4  = (const float*)d_in[14];
    const float* b4  = (const float*)d_in[15];
    const float* g4  = (const float*)d_in[16];
    const float* be4 = (const float*)d_in[17];
    const float* W5  = (const float*)d_in[18];
    const float* b5  = (const float*)d_in[19];
    const float* g5  = (const float*)d_in[20];
    const float* be5 = (const float*)d_in[21];
    const float* W6  = (const float*)d_in[22];
    const float* b6  = (const float*)d_in[23];
    const float* g6  = (const float*)d_in[24];
    const float* be6 = (const float*)d_in[25];
    const float* W7  = (const float*)d_in[26];
    const float* b7  = (const float*)d_in[27];
    const float* g7  = (const float*)d_in[28];
    const float* be7 = (const float*)d_in[29];

    const int N = in_sizes[0] / 64;

    float* cat = nullptr;
    cudaGetSymbolAddress((void**)&cat, g_cat);

    const int nbd  = (N + 63) / 64;
    const int nbc  = (N + 255) / 256;
    const int nbf  = (N + 127) / 128;

    const int smem_dual = (64 * 68 + 2 * 64 * 68) * 4;                // 52,224
    const int smem_f    = (128 * 68 + 64 * 68) * 4;                   // 52,224
    const int smem_c64  = (256 * 64 + 64 * 32) * 4 + 26 * 32 * 4;     // 77,056
    const int smem_c32  = (256 * 32 + 32 * 32) * 4 + 26 * 32 * 4;     // 40,192
    cudaFuncSetAttribute(blk1_dual_kernel,
                         cudaFuncAttributeMaxDynamicSharedMemorySize, smem_dual);
    cudaFuncSetAttribute(blk1_kernel<256>,
                         cudaFuncAttributeMaxDynamicSharedMemorySize, smem_f);
    cudaFuncSetAttribute(conv_kernel<64>,
                         cudaFuncAttributeMaxDynamicSharedMemorySize, smem_c64);
    cudaFuncSetAttribute(conv_kernel<32>,
                         cudaFuncAttributeMaxDynamicSharedMemorySize, smem_c32);

    // entry list: built once, reused by all 4 convs
    build_list_kernel<<<nbc, 256>>>(nbr, N);
    // f1 | f2 fused
    blk1_dual_kernel<<<nbd, 256, smem_dual>>>(vox, W1, b1, g1, be1,
                                              W2, b2, g2, be2, cat, N);
    // f3..f6 (sparse submanifold convs, chained)
    conv_kernel<64><<<nbc, 256, smem_c64>>>(cat + 64,  256, W3, b3, g3, be3, cat + 128, 256, N);
    conv_kernel<32><<<nbc, 256, smem_c32>>>(cat + 128, 256, W4, b4, g4, be4, cat + 160, 256, N);
    conv_kernel<32><<<nbc, 256, smem_c32>>>(cat + 160, 256, W5, b5, g5, be5, cat + 192, 256, N);
    conv_kernel<32><<<nbc, 256, smem_c32>>>(cat + 192, 256, W6, b6, g6, be6, cat + 224, 256, N);
    // final: blk1 over concat(256) -> out(64)
    blk1_kernel<256><<<nbf, 256, smem_f>>>(cat, 256, W7, b7, g7, be7,
                                           (float*)d_out, 64, N);
}

// round 15
// speedup vs baseline: 1.2235x; 1.0681x over previous
#include <cuda_runtime.h>

#define MAX_N 262144
#define MAX_BLK (MAX_N / 256)
__device__ float g_cat[(size_t)MAX_N * 256];
__device__ float g_accum[(size_t)MAX_N * 32];
__device__ int   g_ent[(size_t)MAX_BLK * 26 * 256];
__device__ int   g_cnt[(size_t)MAX_BLK * 26];

typedef unsigned long long u64;

__device__ __forceinline__ u64 pk2(float a, float b) {
    u64 r;
    asm("mov.b64 %0, {%1, %2};" : "=l"(r)
        : "r"(__float_as_uint(a)), "r"(__float_as_uint(b)));
    return r;
}
__device__ __forceinline__ u64 dup2(float a) {
    u64 r; unsigned ai = __float_as_uint(a);
    asm("mov.b64 %0, {%1, %1};" : "=l"(r) : "r"(ai));
    return r;
}
__device__ __forceinline__ float2 up2(u64 v) {
    unsigned a, b;
    asm("mov.b64 {%0, %1}, %2;" : "=r"(a), "=r"(b) : "l"(v));
    return make_float2(__uint_as_float(a), __uint_as_float(b));
}
__device__ __forceinline__ void fma2(u64& d, u64 a, u64 b) {
    asm("fma.rn.f32x2 %0, %1, %2, %0;" : "+l"(d) : "l"(a), "l"(b));
}
__device__ __forceinline__ u64 addp(u64 a, u64 b) {
    u64 r;
    asm("add.rn.f32x2 %0, %1, %2;" : "=l"(r) : "l"(a), "l"(b));
    return r;
}
__device__ __forceinline__ u64 d2u(double d) { return __double_as_longlong(d); }

// ---------------------------------------------------------------------------
// build_list: compact valid non-self taps into per-(block,k) segments AND
// zero g_accum for the first scatter. Entry = (ni << 8) | local_row.
// ---------------------------------------------------------------------------
__global__ __launch_bounds__(256)
void build_list_kernel(const int* __restrict__ nbr, int N)
{
    __shared__ int snb[256 * 27];
    __shared__ int cnt[26];

    const int t    = threadIdx.x;
    const int lane = t & 31;
    const int base = blockIdx.x * 256;

    // zero accum slice for the first scatter
    {
        float* ac = g_accum + (size_t)(base + t) * 32;
        float4 z = make_float4(0.f, 0.f, 0.f, 0.f);
#pragma unroll
        for (int i = 0; i < 8; i++) ((float4*)ac)[i] = z;
    }

    if (t < 26) cnt[t] = 0;
    for (int i = t; i < 256 * 27; i += 256) {
        long long g = (long long)base * 27 + i;
        int v = -1;
        if (g < (long long)N * 27) v = __ldg(&nbr[g]);
        snb[i] = v;
    }
    __syncthreads();

#pragma unroll
    for (int k = 0; k < 27; k++) {
        if (k == 13) continue;
        const int s  = k - (k > 13);
        const int nb = snb[t * 27 + k];
        const bool valid = nb >= 0;
        unsigned m = __ballot_sync(0xffffffffu, valid);
        if (m) {
            int leader = __ffs(m) - 1;
            int wb = 0;
            if (lane == leader) wb = atomicAdd(&cnt[s], __popc(m));
            wb = __shfl_sync(0xffffffffu, wb, leader);
            if (valid) {
                int pos = wb + __popc(m & ((1u << lane) - 1));
                g_ent[((size_t)blockIdx.x * 26 + s) * 256 + pos] = (nb << 8) | t;
            }
        }
    }
    __syncthreads();
    if (t < 26) g_cnt[blockIdx.x * 26 + t] = cnt[t];
}

// ---------------------------------------------------------------------------
// scatter: warp per (block,seg). No smem, no barriers -> max warp supply.
// W[k] chunk (32 ch-values) in registers; entries walked 2-unrolled;
// results RED'd into g_accum (zeroed by the previous merge / build_list).
// ---------------------------------------------------------------------------
template <int INC>
__global__ __launch_bounds__(256)
void scatter_kernel(const float* __restrict__ x, int ldx,
                    const float* __restrict__ W,   // [27][INC][32]
                    int nseg)
{
    const int g = blockIdx.x * 8 + (threadIdx.x >> 5);
    if (g >= nseg) return;
    const int lane = threadIdx.x & 31;
    const int blk  = g / 26;
    const int s    = g - blk * 26;
    const int n_e  = __ldg(&g_cnt[blk * 26 + s]);
    if (n_e == 0) return;
    const int k    = s + (s >= 13);
    const int base = blk * 256;
    const int* ep  = g_ent + ((size_t)blk * 26 + s) * 256;

#pragma unroll
    for (int h = 0; h < INC / 32; h++) {
        float wreg[32];
        const float* Wk = W + ((size_t)k * INC + h * 32) * 32 + lane;
#pragma unroll
        for (int j = 0; j < 32; j++) wreg[j] = __ldg(Wk + j * 32);
        int e = 0;
        for (; e + 2 <= n_e; e += 2) {
            const int p0 = __ldg(ep + e);
            const int p1 = __ldg(ep + e + 1);
            const float4* xr0 = (const float4*)(x + (size_t)(p0 >> 8) * ldx + h * 32);
            const float4* xr1 = (const float4*)(x + (size_t)(p1 >> 8) * ldx + h * 32);
            float4 a0 = __ldg(xr0 + 0), a1 = __ldg(xr0 + 1);
            float4 a2 = __ldg(xr0 + 2), a3 = __ldg(xr0 + 3);
            float4 a4 = __ldg(xr0 + 4), a5 = __ldg(xr0 + 5);
            float4 a6 = __ldg(xr0 + 6), a7 = __ldg(xr0 + 7);
            float4 b0 = __ldg(xr1 + 0), b1 = __ldg(xr1 + 1);
            float4 b2 = __ldg(xr1 + 2), b3 = __ldg(xr1 + 3);
            float4 b4 = __ldg(xr1 + 4), b5 = __ldg(xr1 + 5);
            float4 b6 = __ldg(xr1 + 6), b7 = __ldg(xr1 + 7);
            float va = a0.x*wreg[0]  + a0.y*wreg[1]  + a0.z*wreg[2]  + a0.w*wreg[3]
                     + a1.x*wreg[4]  + a1.y*wreg[5]  + a1.z*wreg[6]  + a1.w*wreg[7]
                     + a2.x*wreg[8]  + a2.y*wreg[9]  + a2.z*wreg[10] + a2.w*wreg[11]
                     + a3.x*wreg[12] + a3.y*wreg[13] + a3.z*wreg[14] + a3.w*wreg[15]
                     + a4.x*wreg[16] + a4.y*wreg[17] + a4.z*wreg[18] + a4.w*wreg[19]
                     + a5.x*wreg[20] + a5.y*wreg[21] + a5.z*wreg[22] + a5.w*wreg[23]
                     + a6.x*wreg[24] + a6.y*wreg[25] + a6.z*wreg[26] + a6.w*wreg[27]
                     + a7.x*wreg[28] + a7.y*wreg[29] + a7.z*wreg[30] + a7.w*wreg[31];
            float vb = b0.x*wreg[0]  + b0.y*wreg[1]  + b0.z*wreg[2]  + b0.w*wreg[3]
                     + b1.x*wreg[4]  + b1.y*wreg[5]  + b1.z*wreg[6]  + b1.w*wreg[7]
                     + b2.x*wreg[8]  + b2.y*wreg[9]  + b2.z*wreg[10] + b2.w*wreg[11]
                     + b3.x*wreg[12] + b3.y*wreg[13] + b3.z*wreg[14] + b3.w*wreg[15]
                     + b4.x*wreg[16] + b4.y*wreg[17] + b4.z*wreg[18] + b4.w*wreg[19]
                     + b5.x*wreg[20] + b5.y*wreg[21] + b5.z*wreg[22] + b5.w*wreg[23]
                     + b6.x*wreg[24] + b6.y*wreg[25] + b6.z*wreg[26] + b6.w*wreg[27]
                     + b7.x*wreg[28] + b7.y*wreg[29] + b7.z*wreg[30] + b7.w*wreg[31];
            atomicAdd(&g_accum[(size_t)(base + (p0 & 255)) * 32 + lane], va);
            atomicAdd(&g_accum[(size_t)(base + (p1 & 255)) * 32 + lane], vb);
        }
        if (e < n_e) {
            const int p0 = __ldg(ep + e);
            const float4* xr0 = (const float4*)(x + (size_t)(p0 >> 8) * ldx + h * 32);
            float4 a0 = __ldg(xr0 + 0), a1 = __ldg(xr0 + 1);
            float4 a2 = __ldg(xr0 + 2), a3 = __ldg(xr0 + 3);
            float4 a4 = __ldg(xr0 + 4), a5 = __ldg(xr0 + 5);
            float4 a6 = __ldg(xr0 + 6), a7 = __ldg(xr0 + 7);
            float va = a0.x*wreg[0]  + a0.y*wreg[1]  + a0.z*wreg[2]  + a0.w*wreg[3]
                     + a1.x*wreg[4]  + a1.y*wreg[5]  + a1.z*wreg[6]  + a1.w*wreg[7]
                     + a2.x*wreg[8]  + a2.y*wreg[9]  + a2.z*wreg[10] + a2.w*wreg[11]
                     + a3.x*wreg[12] + a3.y*wreg[13] + a3.z*wreg[14] + a3.w*wreg[15]
                     + a4.x*wreg[16] + a4.y*wreg[17] + a4.z*wreg[18] + a4.w*wreg[19]
                     + a5.x*wreg[20] + a5.y*wreg[21] + a5.z*wreg[22] + a5.w*wreg[23]
                     + a6.x*wreg[24] + a6.y*wreg[25] + a6.z*wreg[26] + a6.w*wreg[27]
                     + a7.x*wreg[28] + a7.y*wreg[29] + a7.z*wreg[30] + a7.w*wreg[31];
            atomicAdd(&g_accum[(size_t)(base + (p0 & 255)) * 32 + lane], va);
        }
    }
}

// ---------------------------------------------------------------------------
// merge: dense self tap (k=13) + accum merge + LN(32) + ReLU + store.
// Also zeroes its accum slice for the NEXT layer's scatter.
// 256 rows/block, 256 threads; thread tile 4 rows x 8 ch (f32x2).
// ---------------------------------------------------------------------------
template <int INC>
__global__ __launch_bounds__(256)
void merge_kernel(const float* __restrict__ x, int ldx,
                  const float* __restrict__ W,      // [27][INC][32]
                  const float* __restrict__ bias,
                  const float* __restrict__ gam,
                  const float* __restrict__ bet,
                  float* __restrict__ out, int ldo, int N)
{
    constexpr int ROWS = 256;
    constexpr int U    = INC / 4;
    extern __shared__ float sm[];
    float* Xs = sm;                 // [256][INC] swizzled
    float* Ws = Xs + ROWS * INC;    // [INC][32] self-tap W

    const int t    = threadIdx.x;
    const int base = blockIdx.x * ROWS;

    // stage own row into Xs (swizzled)
    {
        const int row  = base + t;
        const int skey = (t >> 2) & 7;
        const float4* xr = (const float4*)(x + (size_t)row * ldx);
#pragma unroll
        for (int u = 0; u < U; u++) {
            float4 v = make_float4(0.f, 0.f, 0.f, 0.f);
            if (row < N) v = __ldg(xr + u);
            *(float4*)&Xs[t * INC + ((u ^ skey) << 2)] = v;
        }
    }
    // stage self-tap W (k=13)
    {
        const float4* Wk4 = (const float4*)(W + (size_t)13 * INC * 32);
        for (int i = t; i < INC * 8; i += 256)
            ((float4*)Ws)[i] = __ldg(Wk4 + i);
    }
    __syncthreads();

    const int cg  = t & 3;
    const int rg  = t >> 2;                  // 0..63
    const int r0  = rg * 4;
    const int c0  = cg * 8;
    const int key = rg & 7;

    // load accum (written by this layer's scatter, prior launch) and re-zero
    u64 hp[4][4];
#pragma unroll
    for (int rr = 0; rr < 4; rr++) {
        float* ap = g_accum + (size_t)(base + r0 + rr) * 32 + c0;
        double2 q0 = ((const double2*)ap)[0];
        double2 q1 = ((const double2*)ap)[1];
        hp[rr][0] = d2u(q0.x); hp[rr][1] = d2u(q0.y);
        hp[rr][2] = d2u(q1.x); hp[rr][3] = d2u(q1.y);
        float4 z = make_float4(0.f, 0.f, 0.f, 0.f);
        ((float4*)ap)[0] = z;
        ((float4*)ap)[1] = z;
    }

    // dense self tap, register tiled: 4 rows x 8 ch
    u64 acc[4][4];
    {
        u64 b0 = pk2(bias[c0 + 0], bias[c0 + 1]);
        u64 b1 = pk2(bias[c0 + 2], bias[c0 + 3]);
        u64 b2 = pk2(bias[c0 + 4], bias[c0 + 5]);
        u64 b3 = pk2(bias[c0 + 6], bias[c0 + 7]);
#pragma unroll
        for (int rr = 0; rr < 4; rr++) {
            acc[rr][0] = b0; acc[rr][1] = b1; acc[rr][2] = b2; acc[rr][3] = b3;
        }
    }

#pragma unroll
    for (int j0 = 0; j0 < INC; j0 += 4) {
        const int slot = ((j0 >> 2) ^ key) << 2;
        float4 xv[4];
#pragma unroll
        for (int rr = 0; rr < 4; rr++)
            xv[rr] = *(const float4*)&Xs[(r0 + rr) * INC + slot];
#pragma unroll
        for (int jj = 0; jj < 4; jj++) {
            double2 wa = *(const double2*)&Ws[(j0 + jj) * 32 + c0];
            double2 wb = *(const double2*)&Ws[(j0 + jj) * 32 + c0 + 4];
            u64 w0 = d2u(wa.x), w1 = d2u(wa.y);
            u64 w2_ = d2u(wb.x), w3 = d2u(wb.y);
#pragma unroll
            for (int rr = 0; rr < 4; rr++) {
                float xs_ = (jj == 0) ? xv[rr].x : (jj == 1) ? xv[rr].y
                          : (jj == 2) ? xv[rr].z : xv[rr].w;
                u64 xd = dup2(xs_);
                fma2(acc[rr][0], xd, w0);
                fma2(acc[rr][1], xd, w1);
                fma2(acc[rr][2], xd, w2_);
                fma2(acc[rr][3], xd, w3);
            }
        }
    }

    // merge + LN(32) + ReLU + store
    float4 g0 = *(const float4*)&gam[c0], g1 = *(const float4*)&gam[c0 + 4];
    float4 e0 = *(const float4*)&bet[c0], e1 = *(const float4*)&bet[c0 + 4];
#pragma unroll
    for (int rr = 0; rr < 4; rr++) {
        u64 a0 = addp(acc[rr][0], hp[rr][0]);
        u64 a1 = addp(acc[rr][1], hp[rr][1]);
        u64 a2 = addp(acc[rr][2], hp[rr][2]);
        u64 a3 = addp(acc[rr][3], hp[rr][3]);
        float2 v0 = up2(a0), v1 = up2(a1), v2 = up2(a2), v3 = up2(a3);
        float s  = v0.x + v0.y + v1.x + v1.y + v2.x + v2.y + v3.x + v3.y;
        float s2 = v0.x*v0.x + v0.y*v0.y + v1.x*v1.x + v1.y*v1.y
                 + v2.x*v2.x + v2.y*v2.y + v3.x*v3.x + v3.y*v3.y;
#pragma unroll
        for (int o = 2; o > 0; o >>= 1) {
            s  += __shfl_xor_sync(0xffffffffu, s,  o);
            s2 += __shfl_xor_sync(0xffffffffu, s2, o);
        }
        float mu  = s * (1.f / 32.f);
        float var = s2 * (1.f / 32.f) - mu * mu;
        float inv = rsqrtf(var + 1e-5f);
        int grow = base + r0 + rr;
        if (grow < N) {
            float4 o0, o1;
            o0.x = fmaxf((v0.x - mu) * inv * g0.x + e0.x, 0.f);
            o0.y = fmaxf((v0.y - mu) * inv * g0.y + e0.y, 0.f);
            o0.z = fmaxf((v1.x - mu) * inv * g0.z + e0.z, 0.f);
            o0.w = fmaxf((v1.y - mu) * inv * g0.w + e0.w, 0.f);
            o1.x = fmaxf((v2.x - mu) * inv * g1.x + e1.x, 0.f);
            o1.y = fmaxf((v2.y - mu) * inv * g1.y + e1.y, 0.f);
            o1.z = fmaxf((v3.x - mu) * inv * g1.z + e1.z, 0.f);
            o1.w = fmaxf((v3.y - mu) * inv * g1.w + e1.w, 0.f);
            *(float4*)&out[(size_t)grow * ldo + c0]     = o0;
            *(float4*)&out[(size_t)grow * ldo + c0 + 4] = o1;
        }
    }
}

// ---------------------------------------------------------------------------
// blk1_dual: f1 = relu(LN(x@W1+b1)), f2 = relu(LN(x@W2+b2)) in one pass.
// ---------------------------------------------------------------------------
__global__ __launch_bounds__(256)
void blk1_dual_kernel(const float* __restrict__ x,
                      const float* __restrict__ W1, const float* __restrict__ b1,
                      const float* __restrict__ g1, const float* __restrict__ be1,
                      const float* __restrict__ W2, const float* __restrict__ b2,
                      const float* __restrict__ g2, const float* __restrict__ be2,
                      float* __restrict__ out, int N)
{
    constexpr int ROWS = 64, PX = 68, PW = 68;
    extern __shared__ float sm[];
    float* Xs = sm;
    float* Ws = sm + ROWS * PX;

    const int t    = threadIdx.x;
    const int cg   = t & 15;
    const int rg   = t >> 4;
    const int r0   = rg * 4;
    const int half = cg >> 3;
    const int c0   = (cg & 7) * 8;
    const int key  = rg & 7;
    const int base = blockIdx.x * ROWS;

    for (int idx = t; idx < 64 * 16; idx += 256) {
        int j = idx >> 4, q = idx & 15;
        int pq = (q >> 1) + ((q & 1) << 3);
        *(float4*)&Ws[j * PW + pq * 4]            = *(const float4*)&W1[j * 64 + q * 4];
        *(float4*)&Ws[64 * PW + j * PW + pq * 4]  = *(const float4*)&W2[j * 64 + q * 4];
    }
    for (int idx = t; idx < ROWS * 16; idx += 256) {
        int r = idx >> 4, u = idx & 15;
        int row = base + r;
        float4 v = make_float4(0.f, 0.f, 0.f, 0.f);
        if (row < N) v = *(const float4*)&x[(size_t)row * 64 + u * 4];
        *(float4*)&Xs[r * PX + ((u ^ ((r >> 2) & 7)) << 2)] = v;
    }
    __syncthreads();

    const float* Wh = Ws + half * 64 * PW;
    const float* bb = half ? b2 : b1;
    const float* gg = half ? g2 : g1;
    const float* ee = half ? be2 : be1;

    u64 acc[4][4];
    {
        u64 p0 = pk2(bb[c0 + 0], bb[c0 + 1]);
        u64 p1 = pk2(bb[c0 + 2], bb[c0 + 3]);
        u64 p2 = pk2(bb[c0 + 4], bb[c0 + 5]);
        u64 p3 = pk2(bb[c0 + 6], bb[c0 + 7]);
#pragma unroll
        for (int rr = 0; rr < 4; rr++) {
            acc[rr][0] = p0; acc[rr][1] = p1; acc[rr][2] = p2; acc[rr][3] = p3;
        }
    }

#pragma unroll
    for (int j0 = 0; j0 < 64; j0 += 4) {
        const int slot = ((j0 >> 2) ^ key) << 2;
        float4 xv[4];
#pragma unroll
        for (int rr = 0; rr < 4; rr++)
            xv[rr] = *(const float4*)&Xs[(r0 + rr) * PX + slot];
#pragma unroll
        for (int jj = 0; jj < 4; jj++) {
            double2 wa = *(const double2*)&Wh[(j0 + jj) * PW + ((cg & 7) << 2)];
            double2 wb = *(const double2*)&Wh[(j0 + jj) * PW + 32 + ((cg & 7) << 2)];
            u64 w0 = d2u(wa.x), w1 = d2u(wa.y);
            u64 w2_ = d2u(wb.x), w3 = d2u(wb.y);
#pragma unroll
            for (int rr = 0; rr < 4; rr++) {
                float xs_ = (jj == 0) ? xv[rr].x : (jj == 1) ? xv[rr].y
                          : (jj == 2) ? xv[rr].z : xv[rr].w;
                u64 xd = dup2(xs_);
                fma2(acc[rr][0], xd, w0);
                fma2(acc[rr][1], xd, w1);
                fma2(acc[rr][2], xd, w2_);
                fma2(acc[rr][3], xd, w3);
            }
        }
    }

    float4 ga = *(const float4*)&gg[c0], gb = *(const float4*)&gg[c0 + 4];
    float4 ea = *(const float4*)&ee[c0], eb = *(const float4*)&ee[c0 + 4];
#pragma unroll
    for (int rr = 0; rr < 4; rr++) {
        float2 v0 = up2(acc[rr][0]), v1 = up2(acc[rr][1]);
        float2 v2 = up2(acc[rr][2]), v3 = up2(acc[rr][3]);
        float s  = v0.x + v0.y + v1.x + v1.y + v2.x + v2.y + v3.x + v3.y;
        float s2 = v0.x*v0.x + v0.y*v0.y + v1.x*v1.x + v1.y*v1.y
                 + v2.x*v2.x + v2.y*v2.y + v3.x*v3.x + v3.y*v3.y;
#pragma unroll
        for (int o = 4; o > 0; o >>= 1) {
            s  += __shfl_xor_sync(0xffffffffu, s,  o);
            s2 += __shfl_xor_sync(0xffffffffu, s2, o);
        }
        float mu  = s * (1.f / 64.f);
        float var = s2 * (1.f / 64.f) - mu * mu;
        float inv = rsqrtf(var + 1e-5f);
        int row = base + r0 + rr;
        if (row < N) {
            float4 o0, o1;
            o0.x = fmaxf((v0.x - mu) * inv * ga.x + ea.x, 0.f);
            o0.y = fmaxf((v0.y - mu) * inv * ga.y + ea.y, 0.f);
            o0.z = fmaxf((v1.x - mu) * inv * ga.z + ea.z, 0.f);
            o0.w = fmaxf((v1.y - mu) * inv * ga.w + ea.w, 0.f);
            o1.x = fmaxf((v2.x - mu) * inv * gb.x + eb.x, 0.f);
            o1.y = fmaxf((v2.y - mu) * inv * gb.y + eb.y, 0.f);
            o1.z = fmaxf((v3.x - mu) * inv * gb.z + eb.z, 0.f);
            o1.w = fmaxf((v3.y - mu) * inv * gb.w + eb.w, 0.f);
            float* op = &out[(size_t)row * 256 + half * 64 + c0];
            *(float4*)op       = o0;
            *(float4*)(op + 4) = o1;
        }
    }
}

// ---------------------------------------------------------------------------
// blk1 (INC=256 final layer): y = relu(LN(x @ W + b)), outC = 64.
// ---------------------------------------------------------------------------
template <int INC>
__global__ __launch_bounds__(256)
void blk1_kernel(const float* __restrict__ x, int ldx,
                 const float* __restrict__ W,
                 const float* __restrict__ bias,
                 const float* __restrict__ gam,
                 const float* __restrict__ bet,
                 float* __restrict__ out, int ldo, int N)
{
    constexpr int KC = 64;
    constexpr int PX = 68;
    constexpr int PW = 68;
    constexpr int ROWS = 128;
    extern __shared__ float sm[];
    float* Xs = sm;
    float* Ws = sm + ROWS * PX;

    const int t   = threadIdx.x;
    const int cg  = t & 7;
    const int rg  = t >> 3;
    const int r0  = rg * 4;
    const int c0  = cg * 8;
    const int key = rg & 7;
    const int base = blockIdx.x * ROWS;

    u64 acc[4][4];
    {
        u64 b0 = pk2(bias[c0 + 0], bias[c0 + 1]);
        u64 b1 = pk2(bias[c0 + 2], bias[c0 + 3]);
        u64 b2 = pk2(bias[c0 + 4], bias[c0 + 5]);
        u64 b3 = pk2(bias[c0 + 6], bias[c0 + 7]);
#pragma unroll
        for (int rr = 0; rr < 4; rr++) {
            acc[rr][0] = b0; acc[rr][1] = b1; acc[rr][2] = b2; acc[rr][3] = b3;
        }
    }

    for (int k0 = 0; k0 < INC; k0 += KC) {
        __syncthreads();
        for (int idx = t; idx < KC * 16; idx += 256) {
            int j = idx >> 4, q = idx & 15;
            int pq = (q >> 1) + ((q & 1) << 3);
            *(float4*)&Ws[j * PW + pq * 4] =
                *(const float4*)&W[(size_t)(k0 + j) * 64 + q * 4];
        }
        for (int idx = t; idx < ROWS * 16; idx += 256) {
            int r = idx >> 4, u = idx & 15;
            int row = base + r;
            float4 v = make_float4(0.f, 0.f, 0.f, 0.f);
            if (row < N)
                v = *(const float4*)&x[(size_t)row * ldx + k0 + u * 4];
            *(float4*)&Xs[r * PX + ((u ^ ((r >> 2) & 7)) << 2)] = v;
        }
        __syncthreads();

#pragma unroll
        for (int j0 = 0; j0 < KC; j0 += 4) {
            const int slot = ((j0 >> 2) ^ key) << 2;
            float4 xv[4];
#pragma unroll
            for (int rr = 0; rr < 4; rr++)
                xv[rr] = *(const float4*)&Xs[(r0 + rr) * PX + slot];
#pragma unroll
            for (int jj = 0; jj < 4; jj++) {
                double2 wa = *(const double2*)&Ws[(j0 + jj) * PW + (cg << 2)];
                double2 wb = *(const double2*)&Ws[(j0 + jj) * PW + 32 + (cg << 2)];
                u64 w0 = d2u(wa.x), w1 = d2u(wa.y);
                u64 w2_ = d2u(wb.x), w3 = d2u(wb.y);
#pragma unroll
                for (int rr = 0; rr < 4; rr++) {
                    float xs_ = (jj == 0) ? xv[rr].x : (jj == 1) ? xv[rr].y
                              : (jj == 2) ? xv[rr].z : xv[rr].w;
                    u64 xd = dup2(xs_);
                    fma2(acc[rr][0], xd, w0);
                    fma2(acc[rr][1], xd, w1);
                    fma2(acc[rr][2], xd, w2_);
                    fma2(acc[rr][3], xd, w3);
                }
            }
        }
    }

    float4 g0 = *(const float4*)&gam[c0], g1 = *(const float4*)&gam[c0 + 4];
    float4 e0 = *(const float4*)&bet[c0], e1 = *(const float4*)&bet[c0 + 4];
#pragma unroll
    for (int rr = 0; rr < 4; rr++) {
        float2 v0 = up2(acc[rr][0]), v1 = up2(acc[rr][1]);
        float2 v2 = up2(acc[rr][2]), v3 = up2(acc[rr][3]);
        float s  = v0.x + v0.y + v1.x + v1.y + v2.x + v2.y + v3.x + v3.y;
        float s2 = v0.x*v0.x + v0.y*v0.y + v1.x*v1.x + v1.y*v1.y
                 + v2.x*v2.x + v2.y*v2.y + v3.x*v3.x + v3.y*v3.y;
#pragma unroll
        for (int o = 4; o > 0; o >>= 1) {
            s  += __shfl_xor_sync(0xffffffffu, s,  o);
            s2 += __shfl_xor_sync(0xffffffffu, s2, o);
        }
        float mu  = s * (1.f / 64.f);
        float var = s2 * (1.f / 64.f) - mu * mu;
        float inv = rsqrtf(var + 1e-5f);
        int row = base + r0 + rr;
        if (row < N) {
            float4 o0, o1;
            o0.x = fmaxf((v0.x - mu) * inv * g0.x + e0.x, 0.f);
            o0.y = fmaxf((v0.y - mu) * inv * g0.y + e0.y, 0.f);
            o0.z = fmaxf((v1.x - mu) * inv * g0.z + e0.z, 0.f);
            o0.w = fmaxf((v1.y - mu) * inv * g0.w + e0.w, 0.f);
            o1.x = fmaxf((v2.x - mu) * inv * g1.x + e1.x, 0.f);
            o1.y = fmaxf((v2.y - mu) * inv * g1.y + e1.y, 0.f);
            o1.z = fmaxf((v3.x - mu) * inv * g1.z + e1.z, 0.f);
            o1.w = fmaxf((v3.y - mu) * inv * g1.w + e1.w, 0.f);
            *(float4*)&out[(size_t)row * ldo + c0]     = o0;
            *(float4*)&out[(size_t)row * ldo + c0 + 4] = o1;
        }
    }
}

// ---------------------------------------------------------------------------
extern "C" void kernel_launch(void* const* d_in, const int* in_sizes, int n_in,
                              void* d_out, int out_size)
{
    const float* vox = (const float*)d_in[0];
    const int*   nbr = (const int*)d_in[1];
    const float* W1  = (const float*)d_in[2];
    const float* b1  = (const float*)d_in[3];
    const float* g1  = (const float*)d_in[4];
    const float* be1 = (const float*)d_in[5];
    const float* W2  = (const float*)d_in[6];
    const float* b2  = (const float*)d_in[7];
    const float* g2  = (const float*)d_in[8];
    const float* be2 = (const float*)d_in[9];
    const float* W3  = (const float*)d_in[10];
    const float* b3  = (const float*)d_in[11];
    const float* g3  = (const float*)d_in[12];
    const float* be3 = (const float*)d_in[13];
    const float* W4  = (const float*)d_in[14];
    const float* b4  = (const float*)d_in[15];
    const float* g4  = (const float*)d_in[16];
    const float* be4 = (const float*)d_in[17];
    const float* W5  = (const float*)d_in[18];
    const float* b5  = (const float*)d_in[19];
    const float* g5  = (const float*)d_in[20];
    const float* be5 = (const float*)d_in[21];
    const float* W6  = (const float*)d_in[22];
    const float* b6  = (const float*)d_in[23];
    const float* g6  = (const float*)d_in[24];
    const float* be6 = (const float*)d_in[25];
    const float* W7  = (const float*)d_in[26];
    const float* b7  = (const float*)d_in[27];
    const float* g7  = (const float*)d_in[28];
    const float* be7 = (const float*)d_in[29];

    const int N = in_sizes[0] / 64;

    float* cat = nullptr;
    cudaGetSymbolAddress((void**)&cat, g_cat);

    const int nbd  = (N + 63) / 64;
    const int nbc  = (N + 255) / 256;
    const int nbf  = (N + 127) / 128;
    const int nseg = nbc * 26;
    const int nbs  = (nseg + 7) / 8;

    const int smem_dual = (64 * 68 + 2 * 64 * 68) * 4;        // 52,224
    const int smem_f    = (128 * 68 + 64 * 68) * 4;           // 52,224
    const int smem_m64  = (256 * 64 + 64 * 32) * 4;           // 73,728
    const int smem_m32  = (256 * 32 + 32 * 32) * 4;           // 36,864
    cudaFuncSetAttribute(blk1_dual_kernel,
                         cudaFuncAttributeMaxDynamicSharedMemorySize, smem_dual);
    cudaFuncSetAttribute(blk1_kernel<256>,
                         cudaFuncAttributeMaxDynamicSharedMemorySize, smem_f);
    cudaFuncSetAttribute(merge_kernel<64>,
                         cudaFuncAttributeMaxDynamicSharedMemorySize, smem_m64);
    cudaFuncSetAttribute(merge_kernel<32>,
                         cudaFuncAttributeMaxDynamicSharedMemorySize, smem_m32);

    // entry list + accum zero: built once, reused by all 4 convs
    build_list_kernel<<<nbc, 256>>>(nbr, N);
    // f1 | f2 fused
    blk1_dual_kernel<<<nbd, 256, smem_dual>>>(vox, W1, b1, g1, be1,
                                              W2, b2, g2, be2, cat, N);
    // f3..f6: scatter (no-smem, high-occ) + merge (dense+LN, re-zeroes accum)
    scatter_kernel<64><<<nbs, 256>>>(cat + 64, 256, W3, nseg);
    merge_kernel<64><<<nbc, 256, smem_m64>>>(cat + 64, 256, W3, b3, g3, be3, cat + 128, 256, N);
    scatter_kernel<32><<<nbs, 256>>>(cat + 128, 256, W4, nseg);
    merge_kernel<32><<<nbc, 256, smem_m32>>>(cat + 128, 256, W4, b4, g4, be4, cat + 160, 256, N);
    scatter_kernel<32><<<nbs, 256>>>(cat + 160, 256, W5, nseg);
    merge_kernel<32><<<nbc, 256, smem_m32>>>(cat + 160, 256, W5, b5, g5, be5, cat + 192, 256, N);
    scatter_kernel<32><<<nbs, 256>>>(cat + 192, 256, W6, nseg);
    merge_kernel<32><<<nbc, 256, smem_m32>>>(cat + 192, 256, W6, b6, g6, be6, cat + 224, 256, N);
    // final: blk1 over concat(256) -> out(64)
    blk1_kernel<256><<<nbf, 256, smem_f>>>(cat, 256, W7, b7, g7, be7,
                                           (float*)d_out, 64, N);
}